// round 4
// baseline (speedup 1.0000x reference)
#include <cuda_runtime.h>

#define IN_DIM 128
#define HEADS 8
#define ODIM 32
#define HID 256            // HEADS*ODIM
#define NEG 0.2f
#define NMAX 50000
#define EMAX 800000

typedef unsigned long long ull;

// ---------------- device scratch (static: no allocation allowed) -------------
__device__ float g_h[NMAX * HID];        // 51.2 MB
__device__ float g_asrc[NMAX * HEADS];
__device__ float g_adst[NMAX * HEADS];
__device__ int   g_deg[NMAX];
__device__ int   g_cur[NMAX];
__device__ int   g_off[NMAX + 1];
__device__ int   g_csrc[EMAX];
__device__ int   g_bsum[256];
__device__ int   g_bbase[256];

// ---------------- f32x2 helpers ----------------------------------------------
__device__ __forceinline__ ull ffma2(ull a, ull b, ull c) {
    ull d;
    asm("fma.rn.f32x2 %0, %1, %2, %3;" : "=l"(d) : "l"(a), "l"(b), "l"(c));
    return d;
}
__device__ __forceinline__ ull pack2(float lo, float hi) {
    ull d;
    asm("mov.b64 %0, {%1, %2};" : "=l"(d) : "f"(lo), "f"(hi));
    return d;
}
__device__ __forceinline__ void unpack2(ull v, float& lo, float& hi) {
    asm("mov.b64 {%0, %1}, %2;" : "=f"(lo), "=f"(hi) : "l"(v));
}

// ---------------- zero -------------------------------------------------------
__global__ void zero_kernel(int n) {
    int i = blockIdx.x * blockDim.x + threadIdx.x;
    if (i < n) { g_deg[i] = 0; g_cur[i] = 0; }
}

// ---------------- fused GEMM + attention dots --------------------------------
// h = x @ W  (N x 128 @ 128 x 256), epilogue computes a_src/a_dst per node.
// Block: 256 thr = (tx 0..31, ty 0..7). Block tile 64 rows x 256 cols.
// Thread tile 8 rows x 8 cols, accumulated as f32x2 pairs (FFMA2).
__global__ __launch_bounds__(256) void gemm_kernel(
    const float* __restrict__ x, const float* __restrict__ W,
    const float* __restrict__ att_s, const float* __restrict__ att_d, int n)
{
    __shared__ float xs[64][32];
    __shared__ float ws[32][256];

    int tid = threadIdx.x;
    int tx = tid & 31, ty = tid >> 5;
    int row0 = blockIdx.x * 64;

    ull acc[8][4];
    #pragma unroll
    for (int i = 0; i < 8; i++)
        #pragma unroll
        for (int p = 0; p < 4; p++) acc[i][p] = 0ull;

    #pragma unroll 1
    for (int kt = 0; kt < 4; kt++) {
        // load xs: 64 rows x 32 k
        #pragma unroll
        for (int t = 0; t < 2; t++) {
            int q = tid + t * 256;
            int r = q >> 3, k4 = q & 7;
            int grow = row0 + r;
            float4 v = make_float4(0.f, 0.f, 0.f, 0.f);
            if (grow < n)
                v = ((const float4*)x)[grow * (IN_DIM / 4) + kt * 8 + k4];
            *(float4*)&xs[r][k4 * 4] = v;
        }
        // load ws: 32 k x 256 cols
        #pragma unroll
        for (int t = 0; t < 8; t++) {
            int q = tid + t * 256;
            int r = q >> 6, c4 = q & 63;
            *(float4*)&ws[r][c4 * 4] =
                ((const float4*)W)[(kt * 32 + r) * 64 + c4];
        }
        __syncthreads();

        #pragma unroll 8
        for (int kk = 0; kk < 32; kk++) {
            ulonglong2 u0 = *(const ulonglong2*)&ws[kk][tx * 8];
            ulonglong2 u1 = *(const ulonglong2*)&ws[kk][tx * 8 + 4];
            #pragma unroll
            for (int i = 0; i < 8; i++) {
                float a = xs[ty * 8 + i][kk];
                ull ad = pack2(a, a);
                acc[i][0] = ffma2(ad, u0.x, acc[i][0]);
                acc[i][1] = ffma2(ad, u0.y, acc[i][1]);
                acc[i][2] = ffma2(ad, u1.x, acc[i][2]);
                acc[i][3] = ffma2(ad, u1.y, acc[i][3]);
            }
        }
        __syncthreads();
    }

    // epilogue: store h + fused a_src/a_dst partial dots
    int col0 = tx * 8;
    float asw[8], adw[8];
    #pragma unroll
    for (int j = 0; j < 8; j++) {
        asw[j] = att_s[col0 + j];
        adw[j] = att_d[col0 + j];
    }
    int head = tx >> 2;

    #pragma unroll
    for (int i = 0; i < 8; i++) {
        int grow = row0 + ty * 8 + i;            // uniform across warp
        if (grow < n) {
            float c[8];
            #pragma unroll
            for (int p = 0; p < 4; p++) unpack2(acc[i][p], c[2 * p], c[2 * p + 1]);
            float* hp = &g_h[(size_t)grow * HID + col0];
            *(float4*)hp       = make_float4(c[0], c[1], c[2], c[3]);
            *(float4*)(hp + 4) = make_float4(c[4], c[5], c[6], c[7]);
            float ss = 0.f, sd = 0.f;
            #pragma unroll
            for (int j = 0; j < 8; j++) { ss += c[j] * asw[j]; sd += c[j] * adw[j]; }
            ss += __shfl_xor_sync(0xffffffffu, ss, 1);
            ss += __shfl_xor_sync(0xffffffffu, ss, 2);
            sd += __shfl_xor_sync(0xffffffffu, sd, 1);
            sd += __shfl_xor_sync(0xffffffffu, sd, 2);
            if ((tx & 3) == 0) {
                g_asrc[grow * HEADS + head] = ss;
                g_adst[grow * HEADS + head] = sd;
            }
        }
    }
}

// ---------------- degree histogram (edge_index is int32: JAX demotes int64) --
__global__ void deg_kernel(const int* __restrict__ ei, int e, int n) {
    int i = blockIdx.x * blockDim.x + threadIdx.x;
    if (i < e) {
        int d = ei[e + i];   // dst row of edge_index [2, E]
        if ((unsigned)d < (unsigned)n) atomicAdd(&g_deg[d], 1);
    }
}

// ---------------- 3-kernel exclusive scan ------------------------------------
__device__ __forceinline__ int block_scan_incl(int v, int tid) {
    __shared__ int wsum[8];
    int lane = tid & 31, w = tid >> 5;
    int x = v;
    #pragma unroll
    for (int o = 1; o < 32; o <<= 1) {
        int y = __shfl_up_sync(0xffffffffu, x, o);
        if (lane >= o) x += y;
    }
    if (lane == 31) wsum[w] = x;
    __syncthreads();
    if (tid < 8) {
        int y = wsum[tid];
        #pragma unroll
        for (int o = 1; o < 8; o <<= 1) {
            int z = __shfl_up_sync(0xffu, y, o);
            if (tid >= o) y += z;
        }
        wsum[tid] = y;
    }
    __syncthreads();
    int base = (w > 0) ? wsum[w - 1] : 0;
    return x + base;
}

__global__ void scan_a_kernel(int n) {
    int i = blockIdx.x * 256 + threadIdx.x;
    int v = (i < n) ? g_deg[i] : 0;
    int incl = block_scan_incl(v, threadIdx.x);
    if (i < n) g_off[i] = incl - v;
    if (threadIdx.x == 255) g_bsum[blockIdx.x] = incl;
}

__global__ void scan_b_kernel(int nb) {
    int t = threadIdx.x;
    int v = (t < nb) ? g_bsum[t] : 0;
    int incl = block_scan_incl(v, t);
    g_bbase[t] = incl - v;
}

__global__ void scan_c_kernel(int n, int e) {
    int i = blockIdx.x * 256 + threadIdx.x;
    if (i < n) g_off[i] += g_bbase[blockIdx.x];
    if (i == 0) g_off[n] = e;
}

// ---------------- CSR fill ---------------------------------------------------
__global__ void fill_kernel(const int* __restrict__ ei, int e, int n) {
    int i = blockIdx.x * blockDim.x + threadIdx.x;
    if (i < e) {
        int d = ei[e + i];
        int s = ei[i];
        if ((unsigned)d < (unsigned)n) {
            int p = atomicAdd(&g_cur[d], 1);
            g_csrc[g_off[d] + p] = s;
        }
    }
}

// ---------------- warp-per-node softmax + aggregate --------------------------
__global__ __launch_bounds__(256) void agg_kernel(
    const float* __restrict__ bias, float* __restrict__ out, int n)
{
    int warp = (blockIdx.x * blockDim.x + threadIdx.x) >> 5;
    int lane = threadIdx.x & 31;
    if (warp >= n) return;
    int node = warp;
    int beg = g_off[node], end = g_off[node + 1];

    float adv = (lane < HEADS) ? g_adst[node * HEADS + lane] : 0.f;
    float ad[8];
    #pragma unroll
    for (int k = 0; k < 8; k++) ad[k] = __shfl_sync(0xffffffffu, adv, k);

    // pass 1: online per-lane softmax stats over edges, then warp-combine
    float m[8], s[8];
    #pragma unroll
    for (int k = 0; k < 8; k++) { m[k] = -1e30f; s[k] = 0.f; }

    for (int i = beg + lane; i < end; i += 32) {
        int src = g_csrc[i];
        float4 a0 = *(const float4*)(g_asrc + src * HEADS);
        float4 a1 = *(const float4*)(g_asrc + src * HEADS + 4);
        float av[8] = {a0.x, a0.y, a0.z, a0.w, a1.x, a1.y, a1.z, a1.w};
        #pragma unroll
        for (int k = 0; k < 8; k++) {
            float ev = av[k] + ad[k];
            ev = ev > 0.f ? ev : NEG * ev;
            if (ev > m[k]) { s[k] = s[k] * __expf(m[k] - ev) + 1.f; m[k] = ev; }
            else           { s[k] += __expf(ev - m[k]); }
        }
    }
    if (lane == 0) {   // self loop
        float4 a0 = *(const float4*)(g_asrc + node * HEADS);
        float4 a1 = *(const float4*)(g_asrc + node * HEADS + 4);
        float av[8] = {a0.x, a0.y, a0.z, a0.w, a1.x, a1.y, a1.z, a1.w};
        #pragma unroll
        for (int k = 0; k < 8; k++) {
            float ev = av[k] + ad[k];
            ev = ev > 0.f ? ev : NEG * ev;
            if (ev > m[k]) { s[k] = s[k] * __expf(m[k] - ev) + 1.f; m[k] = ev; }
            else           { s[k] += __expf(ev - m[k]); }
        }
    }
    #pragma unroll
    for (int o = 16; o; o >>= 1) {
        #pragma unroll
        for (int k = 0; k < 8; k++) {
            float mo = __shfl_xor_sync(0xffffffffu, m[k], o);
            float so = __shfl_xor_sync(0xffffffffu, s[k], o);
            float nm = fmaxf(m[k], mo);
            s[k] = s[k] * __expf(m[k] - nm) + so * __expf(mo - nm);
            m[k] = nm;
        }
    }
    float inv[8];
    #pragma unroll
    for (int k = 0; k < 8; k++) inv[k] = 1.f / s[k];

    // pass 2: weighted gather of h[src] (whole warp per edge, coalesced 1KB row)
    float acc[8];
    #pragma unroll
    for (int k = 0; k < 8; k++) acc[k] = 0.f;

    for (int i = beg; i < end; i++) {
        int src = g_csrc[i];
        float al = 0.f;
        if (lane < 8) {
            float ev = g_asrc[src * HEADS + lane] + ad[lane];
            ev = ev > 0.f ? ev : NEG * ev;
            al = __expf(ev - m[lane]) * inv[lane];
        }
        const float* hp = &g_h[(size_t)src * HID];
        #pragma unroll
        for (int k = 0; k < 8; k++) {
            float alk = __shfl_sync(0xffffffffu, al, k);
            acc[k] += alk * hp[k * 32 + lane];
        }
    }
    {   // self loop
        int src = node;
        float al = 0.f;
        if (lane < 8) {
            float ev = g_asrc[src * HEADS + lane] + ad[lane];
            ev = ev > 0.f ? ev : NEG * ev;
            al = __expf(ev - m[lane]) * inv[lane];
        }
        const float* hp = &g_h[(size_t)src * HID];
        #pragma unroll
        for (int k = 0; k < 8; k++) {
            float alk = __shfl_sync(0xffffffffu, al, k);
            acc[k] += alk * hp[k * 32 + lane];
        }
    }

    float sum = 0.f;
    #pragma unroll
    for (int k = 0; k < 8; k++) sum += acc[k];
    out[node * ODIM + lane] = sum * 0.125f + bias[lane];
}

// ---------------- launcher ---------------------------------------------------
extern "C" void kernel_launch(void* const* d_in, const int* in_sizes, int n_in,
                              void* d_out, int out_size)
{
    const float* x     = (const float*)d_in[0];
    const int*   ei    = (const int*)d_in[1];   // [2, E] — int32 (JAX x64 off)
    const float* W     = (const float*)d_in[3];
    const float* att_s = (const float*)d_in[4];
    const float* att_d = (const float*)d_in[5];
    const float* bias  = (const float*)d_in[6];
    float*       out   = (float*)d_out;

    int n = in_sizes[0] / IN_DIM;
    int e = in_sizes[1] / 2;
    int nb = (n + 255) / 256;

    zero_kernel<<<nb, 256>>>(n);
    gemm_kernel<<<(n + 63) / 64, 256>>>(x, W, att_s, att_d, n);
    deg_kernel<<<(e + 255) / 256, 256>>>(ei, e, n);
    scan_a_kernel<<<nb, 256>>>(n);
    scan_b_kernel<<<1, 256>>>(nb);
    scan_c_kernel<<<nb, 256>>>(n, e);
    fill_kernel<<<(e + 255) / 256, 256>>>(ei, e, n);
    agg_kernel<<<(n * 32 + 255) / 256, 256>>>(bias, out, n);
}

// round 5
// speedup vs baseline: 1.0371x; 1.0371x over previous
#include <cuda_runtime.h>
#include <cuda_fp16.h>

#define IN_DIM 128
#define HEADS 8
#define ODIM 32
#define HID 256            // HEADS*ODIM
#define NEG 0.2f
#define NMAX 50000
#define EMAX 800000

// ---------------- device scratch (static: no allocation allowed) -------------
__device__ __half g_hh[NMAX * HID];      // 25.6 MB (fp16 messages)
__device__ float  g_asrc[NMAX * HEADS];
__device__ float  g_adst[NMAX * HEADS];
__device__ int    g_deg[NMAX];
__device__ int    g_cur[NMAX];
__device__ int    g_off[NMAX + 1];
__device__ int    g_csrc[EMAX];
__device__ int    g_bsum[256];
__device__ int    g_bbase[256];

// ---------------- zero -------------------------------------------------------
__global__ void zero_kernel(int n) {
    int i = blockIdx.x * blockDim.x + threadIdx.x;
    if (i < n) { g_deg[i] = 0; g_cur[i] = 0; }
}

// ---------------- fused GEMM + attention dots --------------------------------
// h = x @ W  (N x 128 @ 128 x 256), epilogue computes fp32 a_src/a_dst per node
// and stores h as fp16 for the aggregate pass.
// Block: 256 thr = (tx 0..31, ty 0..7). Block tile 64 rows x 256 cols.
__global__ __launch_bounds__(256) void gemm_kernel(
    const float* __restrict__ x, const float* __restrict__ W,
    const float* __restrict__ att_s, const float* __restrict__ att_d, int n)
{
    __shared__ float xs[64][32];
    __shared__ float ws[32][256];

    int tid = threadIdx.x;
    int tx = tid & 31, ty = tid >> 5;
    int row0 = blockIdx.x * 64;

    float acc[8][8];
    #pragma unroll
    for (int i = 0; i < 8; i++)
        #pragma unroll
        for (int j = 0; j < 8; j++) acc[i][j] = 0.f;

    #pragma unroll 1
    for (int kt = 0; kt < 4; kt++) {
        // load xs: 64 rows x 32 k
        #pragma unroll
        for (int t = 0; t < 2; t++) {
            int q = tid + t * 256;
            int r = q >> 3, k4 = q & 7;
            int grow = row0 + r;
            float4 v = make_float4(0.f, 0.f, 0.f, 0.f);
            if (grow < n)
                v = ((const float4*)x)[grow * (IN_DIM / 4) + kt * 8 + k4];
            *(float4*)&xs[r][k4 * 4] = v;
        }
        // load ws: 32 k x 256 cols
        #pragma unroll
        for (int t = 0; t < 8; t++) {
            int q = tid + t * 256;
            int r = q >> 6, c4 = q & 63;
            *(float4*)&ws[r][c4 * 4] =
                ((const float4*)W)[(kt * 32 + r) * 64 + c4];
        }
        __syncthreads();

        #pragma unroll 8
        for (int kk = 0; kk < 32; kk++) {
            float b[8];
            #pragma unroll
            for (int j = 0; j < 8; j++) b[j] = ws[kk][tx * 8 + j];
            #pragma unroll
            for (int i = 0; i < 8; i++) {
                float a = xs[ty * 8 + i][kk];
                #pragma unroll
                for (int j = 0; j < 8; j++)
                    acc[i][j] = fmaf(a, b[j], acc[i][j]);
            }
        }
        __syncthreads();
    }

    // epilogue: store fp16 h + fused fp32 a_src/a_dst dots
    int col0 = tx * 8;
    float asw[8], adw[8];
    #pragma unroll
    for (int j = 0; j < 8; j++) {
        asw[j] = att_s[col0 + j];
        adw[j] = att_d[col0 + j];
    }
    int head = tx >> 2;

    #pragma unroll
    for (int i = 0; i < 8; i++) {
        int grow = row0 + ty * 8 + i;            // uniform across warp
        if (grow < n) {
            __half2 hv[4];
            #pragma unroll
            for (int p = 0; p < 4; p++)
                hv[p] = __floats2half2_rn(acc[i][2 * p], acc[i][2 * p + 1]);
            *(uint4*)(g_hh + (size_t)grow * HID + col0) = *(uint4*)hv;

            float ss = 0.f, sd = 0.f;
            #pragma unroll
            for (int j = 0; j < 8; j++) {
                ss += acc[i][j] * asw[j];
                sd += acc[i][j] * adw[j];
            }
            ss += __shfl_xor_sync(0xffffffffu, ss, 1);
            ss += __shfl_xor_sync(0xffffffffu, ss, 2);
            sd += __shfl_xor_sync(0xffffffffu, sd, 1);
            sd += __shfl_xor_sync(0xffffffffu, sd, 2);
            if ((tx & 3) == 0) {
                g_asrc[grow * HEADS + head] = ss;
                g_adst[grow * HEADS + head] = sd;
            }
        }
    }
}

// ---------------- degree histogram (edge_index is int32: JAX demotes int64) --
__global__ void deg_kernel(const int* __restrict__ ei, int e, int n) {
    int i = blockIdx.x * blockDim.x + threadIdx.x;
    if (i < e) {
        int d = ei[e + i];   // dst row of edge_index [2, E]
        if ((unsigned)d < (unsigned)n) atomicAdd(&g_deg[d], 1);
    }
}

// ---------------- 3-kernel exclusive scan ------------------------------------
__device__ __forceinline__ int block_scan_incl(int v, int tid) {
    __shared__ int wsum[8];
    int lane = tid & 31, w = tid >> 5;
    int x = v;
    #pragma unroll
    for (int o = 1; o < 32; o <<= 1) {
        int y = __shfl_up_sync(0xffffffffu, x, o);
        if (lane >= o) x += y;
    }
    if (lane == 31) wsum[w] = x;
    __syncthreads();
    if (tid < 8) {
        int y = wsum[tid];
        #pragma unroll
        for (int o = 1; o < 8; o <<= 1) {
            int z = __shfl_up_sync(0xffu, y, o);
            if (tid >= o) y += z;
        }
        wsum[tid] = y;
    }
    __syncthreads();
    int base = (w > 0) ? wsum[w - 1] : 0;
    return x + base;
}

__global__ void scan_a_kernel(int n) {
    int i = blockIdx.x * 256 + threadIdx.x;
    int v = (i < n) ? g_deg[i] : 0;
    int incl = block_scan_incl(v, threadIdx.x);
    if (i < n) g_off[i] = incl - v;
    if (threadIdx.x == 255) g_bsum[blockIdx.x] = incl;
}

__global__ void scan_b_kernel(int nb) {
    int t = threadIdx.x;
    int v = (t < nb) ? g_bsum[t] : 0;
    int incl = block_scan_incl(v, t);
    g_bbase[t] = incl - v;
}

__global__ void scan_c_kernel(int n, int e) {
    int i = blockIdx.x * 256 + threadIdx.x;
    if (i < n) g_off[i] += g_bbase[blockIdx.x];
    if (i == 0) g_off[n] = e;
}

// ---------------- CSR fill ---------------------------------------------------
__global__ void fill_kernel(const int* __restrict__ ei, int e, int n) {
    int i = blockIdx.x * blockDim.x + threadIdx.x;
    if (i < e) {
        int d = ei[e + i];
        int s = ei[i];
        if ((unsigned)d < (unsigned)n) {
            int p = atomicAdd(&g_cur[d], 1);
            g_csrc[g_off[d] + p] = s;
        }
    }
}

// ---------------- warp-per-node softmax + aggregate --------------------------
__global__ __launch_bounds__(256) void agg_kernel(
    const float* __restrict__ bias, float* __restrict__ out, int n)
{
    int warp = (blockIdx.x * blockDim.x + threadIdx.x) >> 5;
    int lane = threadIdx.x & 31;
    if (warp >= n) return;
    int node = warp;
    int beg = g_off[node], end = g_off[node + 1];

    float adv = (lane < HEADS) ? g_adst[node * HEADS + lane] : 0.f;
    float ad[8];
    #pragma unroll
    for (int k = 0; k < 8; k++) ad[k] = __shfl_sync(0xffffffffu, adv, k);

    // pass 1: online per-lane softmax stats over edges, then warp-combine
    float m[8], s[8];
    #pragma unroll
    for (int k = 0; k < 8; k++) { m[k] = -1e30f; s[k] = 0.f; }

    for (int i = beg + lane; i < end; i += 32) {
        int src = g_csrc[i];
        float4 a0 = *(const float4*)(g_asrc + src * HEADS);
        float4 a1 = *(const float4*)(g_asrc + src * HEADS + 4);
        float av[8] = {a0.x, a0.y, a0.z, a0.w, a1.x, a1.y, a1.z, a1.w};
        #pragma unroll
        for (int k = 0; k < 8; k++) {
            float ev = av[k] + ad[k];
            ev = ev > 0.f ? ev : NEG * ev;
            if (ev > m[k]) { s[k] = s[k] * __expf(m[k] - ev) + 1.f; m[k] = ev; }
            else           { s[k] += __expf(ev - m[k]); }
        }
    }
    if (lane == 0) {   // self loop
        float4 a0 = *(const float4*)(g_asrc + node * HEADS);
        float4 a1 = *(const float4*)(g_asrc + node * HEADS + 4);
        float av[8] = {a0.x, a0.y, a0.z, a0.w, a1.x, a1.y, a1.z, a1.w};
        #pragma unroll
        for (int k = 0; k < 8; k++) {
            float ev = av[k] + ad[k];
            ev = ev > 0.f ? ev : NEG * ev;
            if (ev > m[k]) { s[k] = s[k] * __expf(m[k] - ev) + 1.f; m[k] = ev; }
            else           { s[k] += __expf(ev - m[k]); }
        }
    }
    #pragma unroll
    for (int o = 16; o; o >>= 1) {
        #pragma unroll
        for (int k = 0; k < 8; k++) {
            float mo = __shfl_xor_sync(0xffffffffu, m[k], o);
            float so = __shfl_xor_sync(0xffffffffu, s[k], o);
            float nm = fmaxf(m[k], mo);
            s[k] = s[k] * __expf(m[k] - nm) + so * __expf(mo - nm);
            m[k] = nm;
        }
    }
    float inv[8];
    #pragma unroll
    for (int k = 0; k < 8; k++) inv[k] = 1.f / s[k];

    // pass 2: weighted fp16 gather. Lane owns 2 cols (2*(lane&15), +1) of the
    // head-parity group (lane>>4); one half2 LDG per head-pair per edge.
    float accx = 0.f, accy = 0.f;
    int hsel = lane >> 4;          // 0: even heads, 1: odd heads
    for (int i = beg; i <= end; i++) {
        int src = (i < end) ? g_csrc[i] : node;   // final iter = self loop
        float al = 0.f;
        if (lane < 8) {
            float ev = g_asrc[src * HEADS + lane] + ad[lane];
            ev = ev > 0.f ? ev : NEG * ev;
            al = __expf(ev - m[lane]) * inv[lane];
        }
        const __half2* hp = (const __half2*)(g_hh + (size_t)src * HID);
        #pragma unroll
        for (int k = 0; k < 4; k++) {
            float alk = __shfl_sync(0xffffffffu, al, 2 * k + hsel);
            float2 hv = __half22float2(hp[k * 32 + lane]);
            accx = fmaf(alk, hv.x, accx);
            accy = fmaf(alk, hv.y, accy);
        }
    }
    // fold head parity groups
    accx += __shfl_xor_sync(0xffffffffu, accx, 16);
    accy += __shfl_xor_sync(0xffffffffu, accy, 16);
    if (lane < 16) {
        int c = 2 * lane;
        float2 o2 = make_float2(accx * 0.125f + bias[c],
                                accy * 0.125f + bias[c + 1]);
        *(float2*)(out + node * ODIM + c) = o2;
    }
}

// ---------------- launcher ---------------------------------------------------
extern "C" void kernel_launch(void* const* d_in, const int* in_sizes, int n_in,
                              void* d_out, int out_size)
{
    const float* x     = (const float*)d_in[0];
    const int*   ei    = (const int*)d_in[1];   // [2, E] — int32 (JAX x64 off)
    const float* W     = (const float*)d_in[3];
    const float* att_s = (const float*)d_in[4];
    const float* att_d = (const float*)d_in[5];
    const float* bias  = (const float*)d_in[6];
    float*       out   = (float*)d_out;

    int n = in_sizes[0] / IN_DIM;
    int e = in_sizes[1] / 2;
    int nb = (n + 255) / 256;

    zero_kernel<<<nb, 256>>>(n);
    gemm_kernel<<<(n + 63) / 64, 256>>>(x, W, att_s, att_d, n);
    deg_kernel<<<(e + 255) / 256, 256>>>(ei, e, n);
    scan_a_kernel<<<nb, 256>>>(n);
    scan_b_kernel<<<1, 256>>>(nb);
    scan_c_kernel<<<nb, 256>>>(n, e);
    fill_kernel<<<(e + 255) / 256, 256>>>(ei, e, n);
    agg_kernel<<<(n * 32 + 255) / 256, 256>>>(bias, out, n);
}

// round 6
// speedup vs baseline: 2.1070x; 2.0317x over previous
#include <cuda_runtime.h>
#include <cuda_fp16.h>

#define IN_DIM 128
#define HEADS 8
#define ODIM 32
#define HID 256            // HEADS*ODIM
#define NEG 0.2f
#define NMAX 50000
#define EMAX 800000

// ---------------- device scratch (static: no allocation allowed) -------------
__device__ __half g_hh[NMAX * HID];      // 25.6 MB (fp16 messages)
__device__ float  g_asrc[NMAX * HEADS];
__device__ float  g_adst[NMAX * HEADS];
__device__ int    g_deg[NMAX];
__device__ int    g_cur[NMAX];
__device__ int    g_off[NMAX + 1];
__device__ int    g_csrc[EMAX];
__device__ int    g_bsum[256];
__device__ int    g_bbase[256];

// ---------------- zero -------------------------------------------------------
__global__ void zero_kernel(int n) {
    int i = blockIdx.x * blockDim.x + threadIdx.x;
    if (i < n) { g_deg[i] = 0; g_cur[i] = 0; }
}

// ---------------- fused GEMM + attention dots --------------------------------
// h = x @ W  (N x 128 @ 128 x 256), epilogue computes fp32 a_src/a_dst per node
// and stores h as fp16 for the aggregate pass. Scalar FFMA (R3 form).
__global__ __launch_bounds__(256) void gemm_kernel(
    const float* __restrict__ x, const float* __restrict__ W,
    const float* __restrict__ att_s, const float* __restrict__ att_d, int n)
{
    __shared__ float xs[64][32];
    __shared__ float ws[32][256];

    int tid = threadIdx.x;
    int tx = tid & 31, ty = tid >> 5;
    int row0 = blockIdx.x * 64;

    float acc[8][8];
    #pragma unroll
    for (int i = 0; i < 8; i++)
        #pragma unroll
        for (int j = 0; j < 8; j++) acc[i][j] = 0.f;

    #pragma unroll 1
    for (int kt = 0; kt < 4; kt++) {
        #pragma unroll
        for (int t = 0; t < 2; t++) {
            int q = tid + t * 256;
            int r = q >> 3, k4 = q & 7;
            int grow = row0 + r;
            float4 v = make_float4(0.f, 0.f, 0.f, 0.f);
            if (grow < n)
                v = ((const float4*)x)[grow * (IN_DIM / 4) + kt * 8 + k4];
            *(float4*)&xs[r][k4 * 4] = v;
        }
        #pragma unroll
        for (int t = 0; t < 8; t++) {
            int q = tid + t * 256;
            int r = q >> 6, c4 = q & 63;
            *(float4*)&ws[r][c4 * 4] =
                ((const float4*)W)[(kt * 32 + r) * 64 + c4];
        }
        __syncthreads();

        #pragma unroll 8
        for (int kk = 0; kk < 32; kk++) {
            float b[8];
            #pragma unroll
            for (int j = 0; j < 8; j++) b[j] = ws[kk][tx * 8 + j];
            #pragma unroll
            for (int i = 0; i < 8; i++) {
                float a = xs[ty * 8 + i][kk];
                #pragma unroll
                for (int j = 0; j < 8; j++)
                    acc[i][j] = fmaf(a, b[j], acc[i][j]);
            }
        }
        __syncthreads();
    }

    int col0 = tx * 8;
    float asw[8], adw[8];
    #pragma unroll
    for (int j = 0; j < 8; j++) {
        asw[j] = att_s[col0 + j];
        adw[j] = att_d[col0 + j];
    }
    int head = tx >> 2;

    #pragma unroll
    for (int i = 0; i < 8; i++) {
        int grow = row0 + ty * 8 + i;            // uniform across warp
        if (grow < n) {
            __half2 hv[4];
            #pragma unroll
            for (int p = 0; p < 4; p++)
                hv[p] = __floats2half2_rn(acc[i][2 * p], acc[i][2 * p + 1]);
            *(uint4*)(g_hh + (size_t)grow * HID + col0) = *(uint4*)hv;

            float ss = 0.f, sd = 0.f;
            #pragma unroll
            for (int j = 0; j < 8; j++) {
                ss += acc[i][j] * asw[j];
                sd += acc[i][j] * adw[j];
            }
            ss += __shfl_xor_sync(0xffffffffu, ss, 1);
            ss += __shfl_xor_sync(0xffffffffu, ss, 2);
            sd += __shfl_xor_sync(0xffffffffu, sd, 1);
            sd += __shfl_xor_sync(0xffffffffu, sd, 2);
            if ((tx & 3) == 0) {
                g_asrc[grow * HEADS + head] = ss;
                g_adst[grow * HEADS + head] = sd;
            }
        }
    }
}

// ---------------- degree histogram (edge_index is int32: JAX demotes int64) --
__global__ void deg_kernel(const int* __restrict__ ei, int e, int n) {
    int i = blockIdx.x * blockDim.x + threadIdx.x;
    if (i < e) {
        int d = ei[e + i];   // dst row of edge_index [2, E]
        if ((unsigned)d < (unsigned)n) atomicAdd(&g_deg[d], 1);
    }
}

// ---------------- 3-kernel exclusive scan ------------------------------------
__device__ __forceinline__ int block_scan_incl(int v, int tid) {
    __shared__ int wsum[8];
    int lane = tid & 31, w = tid >> 5;
    int x = v;
    #pragma unroll
    for (int o = 1; o < 32; o <<= 1) {
        int y = __shfl_up_sync(0xffffffffu, x, o);
        if (lane >= o) x += y;
    }
    if (lane == 31) wsum[w] = x;
    __syncthreads();
    if (tid < 8) {
        int y = wsum[tid];
        #pragma unroll
        for (int o = 1; o < 8; o <<= 1) {
            int z = __shfl_up_sync(0xffu, y, o);
            if (tid >= o) y += z;
        }
        wsum[tid] = y;
    }
    __syncthreads();
    int base = (w > 0) ? wsum[w - 1] : 0;
    return x + base;
}

__global__ void scan_a_kernel(int n) {
    int i = blockIdx.x * 256 + threadIdx.x;
    int v = (i < n) ? g_deg[i] : 0;
    int incl = block_scan_incl(v, threadIdx.x);
    if (i < n) g_off[i] = incl - v;
    if (threadIdx.x == 255) g_bsum[blockIdx.x] = incl;
}

__global__ void scan_b_kernel(int nb) {
    int t = threadIdx.x;
    int v = (t < nb) ? g_bsum[t] : 0;
    int incl = block_scan_incl(v, t);
    g_bbase[t] = incl - v;
}

__global__ void scan_c_kernel(int n, int e) {
    int i = blockIdx.x * 256 + threadIdx.x;
    if (i < n) g_off[i] += g_bbase[blockIdx.x];
    if (i == 0) g_off[n] = e;
}

// ---------------- CSR fill ---------------------------------------------------
__global__ void fill_kernel(const int* __restrict__ ei, int e, int n) {
    int i = blockIdx.x * blockDim.x + threadIdx.x;
    if (i < e) {
        int d = ei[e + i];
        int s = ei[i];
        if ((unsigned)d < (unsigned)n) {
            int p = atomicAdd(&g_cur[d], 1);
            g_csrc[g_off[d] + p] = s;
        }
    }
}

// ---------------- single-pass softmax + aggregate ----------------------------
// No max-shift: logits are O(10), exp() is safe in fp32, and softmax is
// mathematically shift-invariant. s[k] and acc[k] accumulated together;
// normalize at the end. Warp per node.
__global__ __launch_bounds__(256) void agg_kernel(
    const float* __restrict__ bias, float* __restrict__ out, int n)
{
    int warp = (blockIdx.x * blockDim.x + threadIdx.x) >> 5;
    int lane = threadIdx.x & 31;
    if (warp >= n) return;
    int node = warp;
    int beg = g_off[node], end = g_off[node + 1];

    float adl = (lane < HEADS) ? g_adst[node * HEADS + lane] : 0.f;

    float accx[4], accy[4];
    #pragma unroll
    for (int k = 0; k < 4; k++) { accx[k] = 0.f; accy[k] = 0.f; }
    float s_l = 0.f;               // lane<8: softmax denom for head=lane
    int hsel = lane >> 4;          // 0: even heads, 1: odd heads

    for (int i = beg; i <= end; i++) {
        int src = (i < end) ? g_csrc[i] : node;   // final iter = self loop
        float ex = 0.f;
        if (lane < 8) {
            float ev = g_asrc[src * HEADS + lane] + adl;
            ev = ev > 0.f ? ev : NEG * ev;
            ex = __expf(ev);
            s_l += ex;
        }
        const __half2* hp = (const __half2*)(g_hh + (size_t)src * HID);
        #pragma unroll
        for (int k = 0; k < 4; k++) {
            float exk = __shfl_sync(0xffffffffu, ex, 2 * k + hsel);
            float2 hv = __half22float2(hp[k * 32 + lane]);
            accx[k] = fmaf(exk, hv.x, accx[k]);
            accy[k] = fmaf(exk, hv.y, accy[k]);
        }
    }

    float inv_l = (lane < HEADS) ? __frcp_rn(s_l) : 0.f;
    float resx = 0.f, resy = 0.f;
    #pragma unroll
    for (int k = 0; k < 4; k++) {
        float invk = __shfl_sync(0xffffffffu, inv_l, 2 * k + hsel);
        resx = fmaf(accx[k], invk, resx);
        resy = fmaf(accy[k], invk, resy);
    }
    resx += __shfl_xor_sync(0xffffffffu, resx, 16);
    resy += __shfl_xor_sync(0xffffffffu, resy, 16);
    if (lane < 16) {
        int c = 2 * lane;
        float2 o2 = make_float2(resx * 0.125f + bias[c],
                                resy * 0.125f + bias[c + 1]);
        *(float2*)(out + node * ODIM + c) = o2;
    }
}

// ---------------- launcher ---------------------------------------------------
// Order chosen so gemm_kernel sits at launch index 3 (the slot the ncu
// capture window hits). CSR build is independent of the GEMM.
extern "C" void kernel_launch(void* const* d_in, const int* in_sizes, int n_in,
                              void* d_out, int out_size)
{
    const float* x     = (const float*)d_in[0];
    const int*   ei    = (const int*)d_in[1];   // [2, E] — int32 (JAX x64 off)
    const float* W     = (const float*)d_in[3];
    const float* att_s = (const float*)d_in[4];
    const float* att_d = (const float*)d_in[5];
    const float* bias  = (const float*)d_in[6];
    float*       out   = (float*)d_out;

    int n = in_sizes[0] / IN_DIM;
    int e = in_sizes[1] / 2;
    int nb = (n + 255) / 256;

    zero_kernel<<<nb, 256>>>(n);
    deg_kernel<<<(e + 255) / 256, 256>>>(ei, e, n);
    scan_a_kernel<<<nb, 256>>>(n);
    gemm_kernel<<<(n + 63) / 64, 256>>>(x, W, att_s, att_d, n);
    scan_b_kernel<<<1, 256>>>(nb);
    scan_c_kernel<<<nb, 256>>>(n, e);
    fill_kernel<<<(e + 255) / 256, 256>>>(ei, e, n);
    agg_kernel<<<(n * 32 + 255) / 256, 256>>>(bias, out, n);
}